// round 3
// baseline (speedup 1.0000x reference)
#include <cuda_runtime.h>
#include <cstdint>

// ---------------- problem constants ----------------
#define C_CH    321
#define D_K     512
#define P_OUT   720
#define N_B     64          // batch == GEMM M
#define BN      128         // p-tile == GEMM N
#define BK      32          // k-chunk
#define KCHUNKS (D_K / BK)  // 16
#define STAGES  4
#define NTHREADS 512

// ---------------- smem layout (floats, padded strides: bank-conflict-free frags) ----
#define A_STRIDE 36                       // 64 rows x 36 floats
#define B_STRIDE 136                      // 32 rows x 136 floats
#define A_STAGE_BYTES (N_B * A_STRIDE * 4)   //  9216
#define B_STAGE_BYTES (BK * B_STRIDE * 4)    // 17408
#define B_BASE        (STAGES * A_STAGE_BYTES)              // 36864
#define SMEM_BYTES    (B_BASE + STAGES * B_STAGE_BYTES)     // 106496

// ---------------- helpers ----------------
__device__ __forceinline__ uint32_t smem_to_u32(const void* p) {
    uint32_t a;
    asm("{ .reg .u64 t; cvta.to.shared.u64 t, %1; cvt.u32.u64 %0, t; }" : "=r"(a) : "l"(p));
    return a;
}
__device__ __forceinline__ uint32_t f2tf32(float f) {
    uint32_t u;
    asm("cvt.rna.tf32.f32 %0, %1;" : "=r"(u) : "f"(f));
    return u;
}
#define CP_ASYNC16(dst, src) \
    asm volatile("cp.async.cg.shared.global [%0], [%1], 16;" :: "r"(dst), "l"(src))
#define CP_ASYNC16_Z(dst, src, sz) \
    asm volatile("cp.async.cg.shared.global [%0], [%1], 16, %2;" :: "r"(dst), "l"(src), "r"(sz))
#define CP_COMMIT()  asm volatile("cp.async.commit_group;" ::: "memory")
#define CP_WAIT3()   asm volatile("cp.async.wait_group 3;" ::: "memory")

__device__ __forceinline__ void mma_tf32(float* acc, const uint32_t* a, const uint32_t* b) {
    asm volatile(
        "mma.sync.aligned.m16n8k8.row.col.f32.tf32.tf32.f32 "
        "{%0,%1,%2,%3}, {%4,%5,%6,%7}, {%8,%9}, {%0,%1,%2,%3};"
        : "+f"(acc[0]), "+f"(acc[1]), "+f"(acc[2]), "+f"(acc[3])
        : "r"(a[0]), "r"(a[1]), "r"(a[2]), "r"(a[3]), "r"(b[0]), "r"(b[1]));
}

// ---------------- kernel ----------------
// CTA (blockIdx.x = p-tile, blockIdx.y = channel c):
//   out[b, c, p0:p0+128] = x[b, c, :] @ W[c, :, p0:p0+128] + bias[c, p0:p0+128]
// GEMM: M=64 (batch) x N=128 (p) x K=512, tf32 mma.sync.
// 16 warps in a 4x4 grid (warp tile 16x32), 4-stage cp.async pipeline.
__global__ void __launch_bounds__(NTHREADS, 2)
pc_linear_mma(const float* __restrict__ x,
              const float* __restrict__ W,
              const float* __restrict__ bias,
              float* __restrict__ out)
{
    extern __shared__ float sm[];
    const uint32_t sbase = smem_to_u32(sm);

    const int tid  = threadIdx.x;
    const int lane = tid & 31;
    const int wid  = tid >> 5;
    const int gid  = lane >> 2;   // fragment group id (0..7)
    const int tig  = lane & 3;    // thread in group (0..3)
    const int wm   = wid >> 2;    // warp row (0..3) -> m0 = wm*16
    const int wn   = wid & 3;     // warp col (0..3) -> n0 = wn*32
    const int c    = blockIdx.y;
    const int p0   = blockIdx.x * BN;

    const float* xc = x + (size_t)c * D_K;                   // + b*(C*D) per row
    const float* Wc = W + (size_t)c * ((size_t)D_K * P_OUT); // [k][p]

    // ---- cp.async issue for one K-chunk into one stage ----
    auto issue = [&](int chunk, int stage) {
        const int k0 = chunk * BK;
        // A tile: x rows b=0..63, k0..k0+31 -> 64*32*4B = 512 x 16B (one per thread)
        const uint32_t abase = sbase + (uint32_t)stage * A_STAGE_BYTES;
        {
            const int r   = tid >> 3;          // batch row
            const int col = (tid & 7) * 4;     // k offset
            const float* src = xc + (size_t)r * (C_CH * D_K) + k0 + col;
            CP_ASYNC16(abase + (uint32_t)(r * A_STRIDE + col) * 4, src);
        }
        // B tile: W rows k0..k0+31, p0..p0+127 -> 1024 x 16B (two per thread); zero-fill OOB
        const uint32_t bbase = sbase + B_BASE + (uint32_t)stage * B_STAGE_BYTES;
#pragma unroll
        for (int j = 0; j < 2; ++j) {
            const int id  = tid + j * NTHREADS;
            const int r   = id >> 5;          // k row
            const int col = (id & 31) * 4;    // p offset
            const float* src = Wc + (size_t)(k0 + r) * P_OUT + p0 + col;
            const int sz = (p0 + col < P_OUT) ? 16 : 0;
            CP_ASYNC16_Z(bbase + (uint32_t)(r * B_STRIDE + col) * 4, src, sz);
        }
    };

    float acc[4][4];   // nt x quad
#pragma unroll
    for (int nt = 0; nt < 4; ++nt)
#pragma unroll
        for (int q = 0; q < 4; ++q) acc[nt][q] = 0.f;

    // ---- pipeline prologue: 3 chunks in flight ----
    issue(0, 0); CP_COMMIT();
    issue(1, 1); CP_COMMIT();
    issue(2, 2); CP_COMMIT();

    // ---- mainloop ----
#pragma unroll 1
    for (int i = 0; i < KCHUNKS; ++i) {
        if (i + 3 < KCHUNKS) issue(i + 3, (i + 3) % STAGES);
        CP_COMMIT();              // commit every iter (possibly empty group)
        CP_WAIT3();               // chunk i landed
        __syncthreads();

        const float* As = sm + (size_t)(i % STAGES) * (A_STAGE_BYTES / 4);
        const float* Bs = sm + (B_BASE / 4) + (size_t)(i % STAGES) * (B_STAGE_BYTES / 4);

#pragma unroll
        for (int ks = 0; ks < 4; ++ks) {
            const int k = ks * 8;
            uint32_t af[4], bf[4][2];
            {
                const int r  = wm * 16 + gid;
                const int cc = k + tig;
                af[0] = f2tf32(As[r * A_STRIDE + cc]);
                af[1] = f2tf32(As[(r + 8) * A_STRIDE + cc]);
                af[2] = f2tf32(As[r * A_STRIDE + cc + 4]);
                af[3] = f2tf32(As[(r + 8) * A_STRIDE + cc + 4]);
            }
#pragma unroll
            for (int nt = 0; nt < 4; ++nt) {
                const int col = wn * 32 + nt * 8 + gid;
                const int kb  = k + tig;
                bf[nt][0] = f2tf32(Bs[kb * B_STRIDE + col]);
                bf[nt][1] = f2tf32(Bs[(kb + 4) * B_STRIDE + col]);
            }
#pragma unroll
            for (int nt = 0; nt < 4; ++nt)
                mma_tf32(acc[nt], af, bf[nt]);
        }
        __syncthreads();          // stage may be overwritten next iter
    }

    // ---- epilogue: D[b][p] + bias[c][p] -> out[b][c][p] ----
#pragma unroll
    for (int nt = 0; nt < 4; ++nt) {
        const int p = p0 + wn * 32 + nt * 8 + tig * 2;
        if (p < P_OUT) {
            const float2 bv = *(const float2*)(bias + (size_t)c * P_OUT + p);
            const int b0r = wm * 16 + gid;
            float2 v0 = make_float2(acc[nt][0] + bv.x, acc[nt][1] + bv.y);
            float2 v1 = make_float2(acc[nt][2] + bv.x, acc[nt][3] + bv.y);
            *(float2*)(out + ((size_t)b0r * C_CH + c) * P_OUT + p)       = v0;
            *(float2*)(out + ((size_t)(b0r + 8) * C_CH + c) * P_OUT + p) = v1;
        }
    }
}

// ---------------- launch ----------------
extern "C" void kernel_launch(void* const* d_in, const int* in_sizes, int n_in,
                              void* d_out, int out_size) {
    const float* x  = (const float*)d_in[0];  // [64, 321, 512]
    const float* W  = (const float*)d_in[1];  // [321, 512, 720]
    const float* bi = (const float*)d_in[2];  // [321, 720]
    float* out      = (float*)d_out;          // [64, 321, 720]

    cudaFuncSetAttribute(pc_linear_mma,
                         cudaFuncAttributeMaxDynamicSharedMemorySize, SMEM_BYTES);
    dim3 grid((P_OUT + BN - 1) / BN, C_CH);   // 6 x 321 = 1926 CTAs
    pc_linear_mma<<<grid, NTHREADS, SMEM_BYTES>>>(x, W, bi, out);
}

// round 4
// speedup vs baseline: 1.2125x; 1.2125x over previous
#include <cuda_runtime.h>
#include <cstdint>

// ---------------- problem constants ----------------
#define C_CH    321
#define D_K     512
#define P_OUT   720
#define N_B     64          // batch == GEMM M
#define BN      128         // p-tile == GEMM N
#define BK      32          // k-chunk
#define KCHUNKS (D_K / BK)  // 16
#define STAGES  4
#define NTHREADS 256

// ---------------- smem layout (floats, padded strides: bank-conflict-free frags) ----
#define A_STRIDE 36                       // 64 rows x 36 floats
#define B_STRIDE 136                      // 32 rows x 136 floats
#define A_STAGE_BYTES (N_B * A_STRIDE * 4)   //  9216
#define B_STAGE_BYTES (BK * B_STRIDE * 4)    // 17408
#define B_BASE        (STAGES * A_STAGE_BYTES)              // 36864
#define SMEM_BYTES    (B_BASE + STAGES * B_STAGE_BYTES)     // 106496

// ---------------- helpers ----------------
__device__ __forceinline__ uint32_t smem_to_u32(const void* p) {
    uint32_t a;
    asm("{ .reg .u64 t; cvta.to.shared.u64 t, %1; cvt.u32.u64 %0, t; }" : "=r"(a) : "l"(p));
    return a;
}
// Round fp32 -> tf32 (HMMA reads top 19 bits; +0x1000 rounds-to-nearest on bit 13,
// carry propagates into exponent correctly). Single IADD instead of 20-cyc cvt.
__device__ __forceinline__ uint32_t rtf32(float f) {
    return __float_as_uint(f) + 0x1000u;
}
#define CP_ASYNC16(dst, src) \
    asm volatile("cp.async.cg.shared.global [%0], [%1], 16;" :: "r"(dst), "l"(src))
#define CP_ASYNC16_Z(dst, src, sz) \
    asm volatile("cp.async.cg.shared.global [%0], [%1], 16, %2;" :: "r"(dst), "l"(src), "r"(sz))
#define CP_COMMIT()  asm volatile("cp.async.commit_group;" ::: "memory")
#define CP_WAIT3()   asm volatile("cp.async.wait_group 3;" ::: "memory")

__device__ __forceinline__ void mma_tf32(float* acc, const uint32_t* a, const uint32_t* b) {
    asm volatile(
        "mma.sync.aligned.m16n8k8.row.col.f32.tf32.tf32.f32 "
        "{%0,%1,%2,%3}, {%4,%5,%6,%7}, {%8,%9}, {%0,%1,%2,%3};"
        : "+f"(acc[0]), "+f"(acc[1]), "+f"(acc[2]), "+f"(acc[3])
        : "r"(a[0]), "r"(a[1]), "r"(a[2]), "r"(a[3]), "r"(b[0]), "r"(b[1]));
}

// ---------------- kernel ----------------
// CTA (blockIdx.x = p-tile, blockIdx.y = channel c):
//   out[b, c, p0:p0+128] = x[b, c, :] @ W[c, :, p0:p0+128] + bias[c, p0:p0+128]
// GEMM: M=64 (batch) x N=128 (p) x K=512, tf32 mma.sync.
// 8 warps in a 2x4 grid (warp tile 32x32), 4-stage cp.async pipeline.
__global__ void __launch_bounds__(NTHREADS, 2)
pc_linear_mma(const float* __restrict__ x,
              const float* __restrict__ W,
              const float* __restrict__ bias,
              float* __restrict__ out)
{
    extern __shared__ float sm[];
    const uint32_t sbase = smem_to_u32(sm);

    const int tid  = threadIdx.x;
    const int lane = tid & 31;
    const int wid  = tid >> 5;
    const int gid  = lane >> 2;   // fragment group id (0..7)
    const int tig  = lane & 3;    // thread in group (0..3)
    const int wm   = wid >> 2;    // warp row (0..1) -> m0 = wm*32
    const int wn   = wid & 3;     // warp col (0..3) -> n0 = wn*32
    const int c    = blockIdx.y;
    const int p0   = blockIdx.x * BN;

    const float* xc = x + (size_t)c * D_K;                   // + b*(C*D) per row
    const float* Wc = W + (size_t)c * ((size_t)D_K * P_OUT); // [k][p]

    // ---- cp.async issue for one K-chunk into one stage ----
    auto issue = [&](int chunk, int stage) {
        const int k0 = chunk * BK;
        // A tile: x rows b=0..63, k0..k0+31 -> 512 x 16B (two per thread)
        const uint32_t abase = sbase + (uint32_t)stage * A_STAGE_BYTES;
#pragma unroll
        for (int i = 0; i < 2; ++i) {
            const int id  = tid + i * NTHREADS;
            const int r   = id >> 3;          // batch row
            const int col = (id & 7) * 4;     // k offset
            const float* src = xc + (size_t)r * (C_CH * D_K) + k0 + col;
            CP_ASYNC16(abase + (uint32_t)(r * A_STRIDE + col) * 4, src);
        }
        // B tile: W rows k0..k0+31, p0..p0+127 -> 1024 x 16B (four per thread); zero-fill OOB
        const uint32_t bbase = sbase + B_BASE + (uint32_t)stage * B_STAGE_BYTES;
#pragma unroll
        for (int j = 0; j < 4; ++j) {
            const int id  = tid + j * NTHREADS;
            const int r   = id >> 5;          // k row
            const int col = (id & 31) * 4;    // p offset
            const float* src = Wc + (size_t)(k0 + r) * P_OUT + p0 + col;
            const int sz = (p0 + col < P_OUT) ? 16 : 0;
            CP_ASYNC16_Z(bbase + (uint32_t)(r * B_STRIDE + col) * 4, src, sz);
        }
    };

    float acc[2][4][4];
#pragma unroll
    for (int mt = 0; mt < 2; ++mt)
#pragma unroll
        for (int nt = 0; nt < 4; ++nt)
#pragma unroll
            for (int q = 0; q < 4; ++q) acc[mt][nt][q] = 0.f;

    // ---- pipeline prologue: 3 chunks in flight ----
    issue(0, 0); CP_COMMIT();
    issue(1, 1); CP_COMMIT();
    issue(2, 2); CP_COMMIT();

    // ---- mainloop ----
#pragma unroll 1
    for (int i = 0; i < KCHUNKS; ++i) {
        if (i + 3 < KCHUNKS) issue(i + 3, (i + 3) % STAGES);
        CP_COMMIT();              // commit every iter (possibly empty group)
        CP_WAIT3();               // chunk i landed
        __syncthreads();

        const float* As = sm + (size_t)(i % STAGES) * (A_STAGE_BYTES / 4);
        const float* Bs = sm + (B_BASE / 4) + (size_t)(i % STAGES) * (B_STAGE_BYTES / 4);

#pragma unroll
        for (int ks = 0; ks < 4; ++ks) {
            const int k = ks * 8;
            uint32_t af[2][4], bf[4][2];
#pragma unroll
            for (int mt = 0; mt < 2; ++mt) {
                const int r  = wm * 32 + mt * 16 + gid;
                const int cc = k + tig;
                af[mt][0] = rtf32(As[r * A_STRIDE + cc]);
                af[mt][1] = rtf32(As[(r + 8) * A_STRIDE + cc]);
                af[mt][2] = rtf32(As[r * A_STRIDE + cc + 4]);
                af[mt][3] = rtf32(As[(r + 8) * A_STRIDE + cc + 4]);
            }
#pragma unroll
            for (int nt = 0; nt < 4; ++nt) {
                const int col = wn * 32 + nt * 8 + gid;
                const int kb  = k + tig;
                bf[nt][0] = rtf32(Bs[kb * B_STRIDE + col]);
                bf[nt][1] = rtf32(Bs[(kb + 4) * B_STRIDE + col]);
            }
#pragma unroll
            for (int mt = 0; mt < 2; ++mt)
#pragma unroll
                for (int nt = 0; nt < 4; ++nt)
                    mma_tf32(acc[mt][nt], af[mt], bf[nt]);
        }
        __syncthreads();          // stage may be overwritten next iter
    }

    // ---- epilogue: D[b][p] + bias[c][p] -> out[b][c][p] ----
#pragma unroll
    for (int nt = 0; nt < 4; ++nt) {
        const int p = p0 + wn * 32 + nt * 8 + tig * 2;
        if (p < P_OUT) {
            const float2 bv = *(const float2*)(bias + (size_t)c * P_OUT + p);
#pragma unroll
            for (int mt = 0; mt < 2; ++mt) {
                const int b0r = wm * 32 + mt * 16 + gid;
                float2 v0 = make_float2(acc[mt][nt][0] + bv.x, acc[mt][nt][1] + bv.y);
                float2 v1 = make_float2(acc[mt][nt][2] + bv.x, acc[mt][nt][3] + bv.y);
                *(float2*)(out + ((size_t)b0r * C_CH + c) * P_OUT + p)       = v0;
                *(float2*)(out + ((size_t)(b0r + 8) * C_CH + c) * P_OUT + p) = v1;
            }
        }
    }
}

// ---------------- launch ----------------
extern "C" void kernel_launch(void* const* d_in, const int* in_sizes, int n_in,
                              void* d_out, int out_size) {
    const float* x  = (const float*)d_in[0];  // [64, 321, 512]
    const float* W  = (const float*)d_in[1];  // [321, 512, 720]
    const float* bi = (const float*)d_in[2];  // [321, 720]
    float* out      = (float*)d_out;          // [64, 321, 720]

    cudaFuncSetAttribute(pc_linear_mma,
                         cudaFuncAttributeMaxDynamicSharedMemorySize, SMEM_BYTES);
    dim3 grid((P_OUT + BN - 1) / BN, C_CH);   // 6 x 321 = 1926 CTAs
    pc_linear_mma<<<grid, NTHREADS, SMEM_BYTES>>>(x, W, bi, out);
}

// round 5
// speedup vs baseline: 1.3378x; 1.1033x over previous
#include <cuda_runtime.h>
#include <cstdint>

// ---------------- problem constants ----------------
#define C_CH    321
#define D_K     512
#define P_OUT   720
#define N_B     64          // batch == GEMM M
#define BN      128         // p-tile == GEMM N
#define BK      32          // k-chunk
#define KCHUNKS (D_K / BK)  // 16
#define STAGES  3
#define NTHREADS 256

// ---------------- smem layout ----------------
// A: 64 rows x 32 floats, XOR-swizzled (no pad). B: 32 rows x 136 floats (padded).
#define A_STAGE_FLOATS (N_B * 32)            // 2048
#define A_STAGE_BYTES  (A_STAGE_FLOATS * 4)  // 8192
#define B_STRIDE 136
#define B_STAGE_BYTES  (BK * B_STRIDE * 4)   // 17408
#define B_BASE         (STAGES * A_STAGE_BYTES)            // 24576
#define SMEM_BYTES     (B_BASE + STAGES * B_STAGE_BYTES)   // 76800 (75 KB)

// ---------------- helpers ----------------
__device__ __forceinline__ uint32_t smem_to_u32(const void* p) {
    uint32_t a;
    asm("{ .reg .u64 t; cvta.to.shared.u64 t, %1; cvt.u32.u64 %0, t; }" : "=r"(a) : "l"(p));
    return a;
}
// fp32 -> tf32 round-to-nearest via mantissa carry add (HMMA reads top 19 bits).
__device__ __forceinline__ uint32_t rtf32(float f) {
    return __float_as_uint(f) + 0x1000u;
}
#define CP_ASYNC16(dst, src) \
    asm volatile("cp.async.cg.shared.global [%0], [%1], 16;" :: "r"(dst), "l"(src))
#define CP_ASYNC16_Z(dst, src, sz) \
    asm volatile("cp.async.cg.shared.global [%0], [%1], 16, %2;" :: "r"(dst), "l"(src), "r"(sz))
#define CP_COMMIT()  asm volatile("cp.async.commit_group;" ::: "memory")
#define CP_WAIT1()   asm volatile("cp.async.wait_group 1;" ::: "memory")

__device__ __forceinline__ void mma_tf32(float* acc, const uint32_t* a, const uint32_t* b) {
    asm volatile(
        "mma.sync.aligned.m16n8k8.row.col.f32.tf32.tf32.f32 "
        "{%0,%1,%2,%3}, {%4,%5,%6,%7}, {%8,%9}, {%0,%1,%2,%3};"
        : "+f"(acc[0]), "+f"(acc[1]), "+f"(acc[2]), "+f"(acc[3])
        : "r"(a[0]), "r"(a[1]), "r"(a[2]), "r"(a[3]), "r"(b[0]), "r"(b[1]));
}

// ---------------- kernel ----------------
// CTA (blockIdx.x = p-tile, blockIdx.y = channel c):
//   out[b, c, p0:p0+128] = x[b, c, :] @ W[c, :, p0:p0+128] + bias[c, p0:p0+128]
// M=64 x N=128 x K=512 tf32 mma.sync; 8 warps (2x4, 32x32 tiles);
// 3-stage cp.async pipeline, ONE barrier per chunk; 3 CTAs/SM.
__global__ void __launch_bounds__(NTHREADS, 3)
pc_linear_mma(const float* __restrict__ x,
              const float* __restrict__ W,
              const float* __restrict__ bias,
              float* __restrict__ out)
{
    extern __shared__ float sm[];
    const uint32_t sbase = smem_to_u32(sm);

    const int tid  = threadIdx.x;
    const int lane = tid & 31;
    const int wid  = tid >> 5;
    const int gid  = lane >> 2;   // fragment group id (0..7)
    const int tig  = lane & 3;    // thread in group (0..3)
    const int wm   = wid >> 2;    // warp row (0..1) -> m0 = wm*32
    const int wn   = wid & 3;     // warp col (0..3) -> n0 = wn*32
    const int c    = blockIdx.y;
    const int p0   = blockIdx.x * BN;

    const float* xc = x + (size_t)c * D_K;
    const float* Wc = W + (size_t)c * ((size_t)D_K * P_OUT);

    // ---- cp.async issue for one K-chunk into one stage ----
    auto issue = [&](int chunk, int stage) {
        const int k0 = chunk * BK;
        // A tile: 64 rows x 32 floats, swizzled: chunk16 index ^= (row & 7)
        const uint32_t abase = sbase + (uint32_t)stage * A_STAGE_BYTES;
#pragma unroll
        for (int i = 0; i < 2; ++i) {
            const int id   = tid + i * NTHREADS;
            const int r    = id >> 3;          // batch row
            const int col4 = (id & 7) * 4;     // k offset (16B chunk)
            const float* src = xc + (size_t)r * (C_CH * D_K) + k0 + col4;
            const uint32_t foff = (uint32_t)(r * 32 + (col4 ^ ((r & 7) * 4)));
            CP_ASYNC16(abase + foff * 4, src);
        }
        // B tile: 32 rows x 128 floats (pad 136); zero-fill OOB p
        const uint32_t bbase = sbase + B_BASE + (uint32_t)stage * B_STAGE_BYTES;
#pragma unroll
        for (int j = 0; j < 4; ++j) {
            const int id  = tid + j * NTHREADS;
            const int r   = id >> 5;          // k row
            const int col = (id & 31) * 4;    // p offset
            const float* src = Wc + (size_t)(k0 + r) * P_OUT + p0 + col;
            const int sz = (p0 + col < P_OUT) ? 16 : 0;
            CP_ASYNC16_Z(bbase + (uint32_t)(r * B_STRIDE + col) * 4, src, sz);
        }
    };

    float acc[2][4][4];
#pragma unroll
    for (int mt = 0; mt < 2; ++mt)
#pragma unroll
        for (int nt = 0; nt < 4; ++nt)
#pragma unroll
            for (int q = 0; q < 4; ++q) acc[mt][nt][q] = 0.f;

    // ---- prologue: 2 chunks in flight ----
    issue(0, 0); CP_COMMIT();
    issue(1, 1); CP_COMMIT();

    // ---- mainloop: ONE barrier per chunk ----
#pragma unroll 1
    for (int i = 0; i < KCHUNKS; ++i) {
        CP_WAIT1();               // chunk i landed (i+1 groups of first 2+i committed)
        __syncthreads();          // publish stage i; proves compute(i-1) done (WAR-safe)
        if (i + 2 < KCHUNKS) issue(i + 2, (i + 2) % STAGES);
        CP_COMMIT();              // commit every iter (possibly empty) keeps ledger exact

        const float* As = sm + (size_t)(i % STAGES) * A_STAGE_FLOATS;
        const float* Bs = sm + (B_BASE / 4) + (size_t)(i % STAGES) * (B_STAGE_BYTES / 4);

#pragma unroll
        for (int ks = 0; ks < 4; ++ks) {
            uint32_t af[2][4], bf[4][2];
            const int c0 = ((2 * ks) ^ gid) * 4 + tig;   // swizzled float offset, chunk 2ks
            const int c1 = c0 ^ 4;                       // chunk 2ks+1
#pragma unroll
            for (int mt = 0; mt < 2; ++mt) {
                const int r = wm * 32 + mt * 16 + gid;   // r & 7 == gid
                af[mt][0] = rtf32(As[r * 32 + c0]);
                af[mt][1] = rtf32(As[(r + 8) * 32 + c0]);
                af[mt][2] = rtf32(As[r * 32 + c1]);
                af[mt][3] = rtf32(As[(r + 8) * 32 + c1]);
            }
            const int k = ks * 8;
#pragma unroll
            for (int nt = 0; nt < 4; ++nt) {
                const int col = wn * 32 + nt * 8 + gid;
                const int kb  = k + tig;
                bf[nt][0] = rtf32(Bs[kb * B_STRIDE + col]);
                bf[nt][1] = rtf32(Bs[(kb + 4) * B_STRIDE + col]);
            }
#pragma unroll
            for (int mt = 0; mt < 2; ++mt)
#pragma unroll
                for (int nt = 0; nt < 4; ++nt)
                    mma_tf32(acc[mt][nt], af[mt], bf[nt]);
        }
    }

    // ---- epilogue: D[b][p] + bias[c][p] -> out[b][c][p] ----
#pragma unroll
    for (int nt = 0; nt < 4; ++nt) {
        const int p = p0 + wn * 32 + nt * 8 + tig * 2;
        if (p < P_OUT) {
            const float2 bv = *(const float2*)(bias + (size_t)c * P_OUT + p);
#pragma unroll
            for (int mt = 0; mt < 2; ++mt) {
                const int b0r = wm * 32 + mt * 16 + gid;
                float2 v0 = make_float2(acc[mt][nt][0] + bv.x, acc[mt][nt][1] + bv.y);
                float2 v1 = make_float2(acc[mt][nt][2] + bv.x, acc[mt][nt][3] + bv.y);
                *(float2*)(out + ((size_t)b0r * C_CH + c) * P_OUT + p)       = v0;
                *(float2*)(out + ((size_t)(b0r + 8) * C_CH + c) * P_OUT + p) = v1;
            }
        }
    }
}

// ---------------- launch ----------------
extern "C" void kernel_launch(void* const* d_in, const int* in_sizes, int n_in,
                              void* d_out, int out_size) {
    const float* x  = (const float*)d_in[0];  // [64, 321, 512]
    const float* W  = (const float*)d_in[1];  // [321, 512, 720]
    const float* bi = (const float*)d_in[2];  // [321, 720]
    float* out      = (float*)d_out;          // [64, 321, 720]

    cudaFuncSetAttribute(pc_linear_mma,
                         cudaFuncAttributeMaxDynamicSharedMemorySize, SMEM_BYTES);
    dim3 grid((P_OUT + BN - 1) / BN, C_CH);   // 6 x 321 = 1926 CTAs
    pc_linear_mma<<<grid, NTHREADS, SMEM_BYTES>>>(x, W, bi, out);
}